// round 8
// baseline (speedup 1.0000x reference)
#include <cuda_runtime.h>
#include <cstdint>

#define NNODES 100000
#define FDIM 192
#define NHEAD 3
#define HDIM 64
#define MRF 266
#define MPAD 288
#define QKF 576
#define NLAYER 4
#define EEDGE 1000000
#define EPSK 1e-3f
#define LNEPS 1e-5f
#define CHN 1056
#define NC 96
#define NKV (CHN / 32)
#define NB128 ((NNODES + 127) / 128)
#define NB64 ((NNODES + 63) / 64)

__device__ float g_qkv[(size_t)NNODES * QKF];
__device__ float g_attn[(size_t)NNODES * FDIM];
__device__ float g_h[(size_t)NNODES * FDIM];
__device__ float g_kvp[(size_t)NHEAD * NC * MPAD * 64];
__device__ float g_ksp[(size_t)NHEAD * NC * MPAD];
__device__ float g_kvT[NHEAD * 64 * MPAD];
__device__ float g_ksum[NHEAD * MPAD];
__device__ float g_wqkv[NLAYER * QKF * FDIM];
__device__ float g_wor[NLAYER * FDIM * FDIM];
__device__ float g_projr[NLAYER * MPAD * HDIM];

__device__ __forceinline__ float rtf(float x) {
    unsigned u; asm("cvt.rna.tf32.f32 %0, %1;" : "=r"(u) : "f"(x));
    return __uint_as_float(u);
}
__device__ __forceinline__ void cpa16(unsigned dst, const float* src, bool p) {
    int sz = p ? 16 : 0;
    asm volatile("cp.async.cg.shared.global [%0], [%1], 16, %2;" :: "r"(dst), "l"(src), "r"(sz));
}
__device__ __forceinline__ void cp_commit() { asm volatile("cp.async.commit_group;"); }
template <int N> __device__ __forceinline__ void cp_wait() {
    asm volatile("cp.async.wait_group %0;" :: "n"(N));
}
__device__ __forceinline__ void mma8(float* c, unsigned a0, unsigned a1, unsigned a2,
                                     unsigned a3, unsigned b0, unsigned b1) {
    asm volatile("mma.sync.aligned.m16n8k8.row.col.f32.tf32.tf32.f32 "
                 "{%0,%1,%2,%3}, {%4,%5,%6,%7}, {%8,%9}, {%0,%1,%2,%3};"
                 : "+f"(c[0]), "+f"(c[1]), "+f"(c[2]), "+f"(c[3])
                 : "r"(a0), "r"(a1), "r"(a2), "r"(a3), "r"(b0), "r"(b1));
}

// ======================= QKV GEMM (128 x BN, round-store) =======================
template <int BN>
__device__ __forceinline__ void stage_gemm(float* sA, const float* A, int lda,
                                           const float* B, int ldb, int brows,
                                           int n0, int o0, int t, int kb)
{
    float* sB = sA + 128 * 36;
    unsigned ua = (unsigned)__cvta_generic_to_shared(sA);
    unsigned ub = (unsigned)__cvta_generic_to_shared(sB);
#pragma unroll
    for (int i = 0; i < 4; i++) {
        int id = t + 256 * i, r = id >> 3, c4 = (id & 7) * 4;
        cpa16(ua + (r * 36 + c4) * 4, A + (size_t)(n0 + r) * lda + kb + c4, (n0 + r) < NNODES);
    }
#pragma unroll
    for (int i = 0; i < BN / 32; i++) {
        int id = t + 256 * i, r = id >> 3, c4 = (id & 7) * 4;
        cpa16(ub + (r * 36 + c4) * 4, B + (size_t)(o0 + r) * ldb + kb + c4, (o0 + r) < brows);
    }
}

template <int BN>
__global__ __launch_bounds__(256) void tc_gemm2(
    const float* __restrict__ A, int lda,
    const float* __restrict__ B, int ldb, int brows,
    float* __restrict__ C, int ldc, int K)
{
    extern __shared__ float sm[];
    constexpr int STG = (128 + BN) * 36;
    constexpr int NS = BN / 16;
    const int t = threadIdx.x, lane = t & 31, warp = t >> 5;
    const int wr = warp >> 1, wc = warp & 1;
    const int n0 = blockIdx.y * 128, o0 = blockIdx.x * BN;

    float acc[2][NS][4];
#pragma unroll
    for (int ms = 0; ms < 2; ms++)
#pragma unroll
        for (int ns = 0; ns < NS; ns++)
#pragma unroll
            for (int j = 0; j < 4; j++) acc[ms][ns][j] = 0.f;

    const int NK = K >> 5;
    stage_gemm<BN>(sm, A, lda, B, ldb, brows, n0, o0, t, 0);
    cp_commit();
    for (int it = 0; it < NK; it++) {
        if (it + 1 < NK) {
            stage_gemm<BN>(sm + ((it + 1) & 1) * STG, A, lda, B, ldb, brows,
                           n0, o0, t, (it + 1) << 5);
            cp_commit(); cp_wait<1>();
        } else {
            cp_wait<0>();
        }
        __syncthreads();
        float* sA = sm + (it & 1) * STG; float* sB = sA + 128 * 36;
#pragma unroll
        for (int kk = 0; kk < 4; kk++) {
            int k0 = kk * 8;
            unsigned bf0[NS], bf1[NS];
#pragma unroll
            for (int ns = 0; ns < NS; ns++) {
                int col = wc * (BN / 2) + ns * 8 + (lane >> 2);
                bf0[ns] = __float_as_uint(sB[col * 36 + k0 + (lane & 3)]);
                bf1[ns] = __float_as_uint(sB[col * 36 + k0 + 4 + (lane & 3)]);
            }
#pragma unroll
            for (int ms = 0; ms < 2; ms++) {
                int row = wr * 32 + ms * 16 + (lane >> 2);
                unsigned a0 = __float_as_uint(sA[row * 36 + k0 + (lane & 3)]);
                unsigned a1 = __float_as_uint(sA[(row + 8) * 36 + k0 + (lane & 3)]);
                unsigned a2 = __float_as_uint(sA[row * 36 + k0 + 4 + (lane & 3)]);
                unsigned a3 = __float_as_uint(sA[(row + 8) * 36 + k0 + 4 + (lane & 3)]);
#pragma unroll
                for (int ns = 0; ns < NS; ns++)
                    mma8(acc[ms][ns], a0, a1, a2, a3, bf0[ns], bf1[ns]);
            }
        }
        __syncthreads();
    }

#pragma unroll
    for (int ms = 0; ms < 2; ms++) {
        int lr = wr * 32 + ms * 16 + (lane >> 2);
#pragma unroll
        for (int half = 0; half < 2; half++) {
            int row = n0 + lr + half * 8;
            if (row >= NNODES) continue;
#pragma unroll
            for (int ns = 0; ns < NS; ns++) {
                int col = o0 + wc * (BN / 2) + ns * 8 + (lane & 3) * 2;
                float v0 = rtf(acc[ms][ns][half * 2 + 0]);
                float v1 = rtf(acc[ms][ns][half * 2 + 1]);
                *(float2*)&C[(size_t)row * ldc + col] = make_float2(v0, v1);
            }
        }
    }
}

// ======================= fused kf-feature + kv split-K =======================
__global__ __launch_bounds__(256) void tc_kvf(const float* __restrict__ proj)
{
    extern __shared__ float sm[];
    float* sPj = sm;                    // 96*68
    float* sK  = sPj + 96 * 68;         // 2 * 32*68
    float* sV  = sK + 2 * 32 * 68;      // 2 * 32*68
    float* sF  = sV + 2 * 32 * 68;      // 32*100

    const int t = threadIdx.x, lane = t & 31, warp = t >> 5;
    const int fwr = warp & 1, fwc = warp >> 1;   // feature map: 2x4
    const int mw = warp & 1, dw = warp >> 1;     // main map: 2x4
    const int m0 = blockIdx.x * 96, chunk = blockIdx.y, head = blockIdx.z;
    const int nbase = chunk * CHN;

    {
        unsigned up = (unsigned)__cvta_generic_to_shared(sPj);
#pragma unroll
        for (int i = 0; i < 6; i++) {
            int id = t + 256 * i, r = id >> 4, c4 = (id & 15) * 4;
            cpa16(up + (r * 68 + c4) * 4, proj + (size_t)(m0 + r) * HDIM + c4, true);
        }
        unsigned uk = (unsigned)__cvta_generic_to_shared(sK);
        unsigned uv = (unsigned)__cvta_generic_to_shared(sV);
#pragma unroll
        for (int i = 0; i < 2; i++) {
            int id = t + 256 * i, r = id >> 4, c4 = (id & 15) * 4, gn = nbase + r;
            cpa16(uk + (r * 68 + c4) * 4, g_qkv + (size_t)gn * QKF + 192 + head * 64 + c4, gn < NNODES);
            cpa16(uv + (r * 68 + c4) * 4, g_qkv + (size_t)gn * QKF + 384 + head * 64 + c4, gn < NNODES);
        }
        cp_commit();
    }

    float acc[3][2][4];
#pragma unroll
    for (int ms = 0; ms < 3; ms++)
#pragma unroll
        for (int ns = 0; ns < 2; ns++)
#pragma unroll
            for (int j = 0; j < 4; j++) acc[ms][ns][j] = 0.f;
    float facc[3][4];
#pragma unroll
    for (int ns = 0; ns < 3; ns++)
#pragma unroll
        for (int j = 0; j < 4; j++) facc[ns][j] = 0.f;
    float sk[3][2] = {{0.f,0.f},{0.f,0.f},{0.f,0.f}};

    for (int it = 0; it < NKV; it++) {
        if (it + 1 < NKV) {
            int b = (it + 1) & 1, nb = nbase + (it + 1) * 32;
            unsigned uk = (unsigned)__cvta_generic_to_shared(sK + b * 32 * 68);
            unsigned uv = (unsigned)__cvta_generic_to_shared(sV + b * 32 * 68);
#pragma unroll
            for (int i = 0; i < 2; i++) {
                int id = t + 256 * i, r = id >> 4, c4 = (id & 15) * 4, gn = nb + r;
                cpa16(uk + (r * 68 + c4) * 4, g_qkv + (size_t)gn * QKF + 192 + head * 64 + c4, gn < NNODES);
                cpa16(uv + (r * 68 + c4) * 4, g_qkv + (size_t)gn * QKF + 384 + head * 64 + c4, gn < NNODES);
            }
            cp_commit(); cp_wait<1>();
        } else {
            cp_wait<0>();
        }
        __syncthreads();
        float* cK = sK + (it & 1) * 32 * 68;
        float* cV = sV + (it & 1) * 32 * 68;

        // feature mma: F(32 n x 96 m) = k_tile(32x64) @ projT
#pragma unroll
        for (int kk = 0; kk < 8; kk++) {
            int k0 = kk * 8;
            int row = fwr * 16 + (lane >> 2);
            unsigned a0 = __float_as_uint(cK[row * 68 + k0 + (lane & 3)]);
            unsigned a1 = __float_as_uint(cK[(row + 8) * 68 + k0 + (lane & 3)]);
            unsigned a2 = __float_as_uint(cK[row * 68 + k0 + 4 + (lane & 3)]);
            unsigned a3 = __float_as_uint(cK[(row + 8) * 68 + k0 + 4 + (lane & 3)]);
#pragma unroll
            for (int ns = 0; ns < 3; ns++) {
                int colm = fwc * 24 + ns * 8 + (lane >> 2);
                unsigned b0 = __float_as_uint(sPj[colm * 68 + k0 + (lane & 3)]);
                unsigned b1 = __float_as_uint(sPj[colm * 68 + k0 + 4 + (lane & 3)]);
                mma8(facc[ns], a0, a1, a2, a3, b0, b1);
            }
        }
        // relu/eps/round, zero invalid rows & padded m, store F [n][m] stride 100
        {
            int rown = fwr * 16 + (lane >> 2);
            int gn0 = nbase + it * 32 + rown, gn1 = gn0 + 8;
#pragma unroll
            for (int ns = 0; ns < 3; ns++) {
                int colm = fwc * 24 + ns * 8 + (lane & 3) * 2;
                int gm = m0 + colm;
                float v0 = (gn0 < NNODES && gm < MRF)     ? rtf(fmaxf(facc[ns][0], 0.f) + EPSK) : 0.f;
                float v1 = (gn0 < NNODES && gm + 1 < MRF) ? rtf(fmaxf(facc[ns][1], 0.f) + EPSK) : 0.f;
                float v2 = (gn1 < NNODES && gm < MRF)     ? rtf(fmaxf(facc[ns][2], 0.f) + EPSK) : 0.f;
                float v3 = (gn1 < NNODES && gm + 1 < MRF) ? rtf(fmaxf(facc[ns][3], 0.f) + EPSK) : 0.f;
                *(float2*)&sF[rown * 100 + colm] = make_float2(v0, v1);
                *(float2*)&sF[(rown + 8) * 100 + colm] = make_float2(v2, v3);
                facc[ns][0] = facc[ns][1] = facc[ns][2] = facc[ns][3] = 0.f;
            }
        }
        __syncthreads();
        // main mma: kv(96 m x 64 d) += F^T(96x32) @ v(32x64); ksum from A-frags
#pragma unroll
        for (int kk = 0; kk < 4; kk++) {
            int k0 = kk * 8;
            unsigned bf0[2], bf1[2];
#pragma unroll
            for (int ns = 0; ns < 2; ns++) {
                int cold = dw * 16 + ns * 8 + (lane >> 2);
                bf0[ns] = __float_as_uint(cV[(k0 + (lane & 3)) * 68 + cold]);
                bf1[ns] = __float_as_uint(cV[(k0 + 4 + (lane & 3)) * 68 + cold]);
            }
#pragma unroll
            for (int ms = 0; ms < 3; ms++) {
                int mcol = mw * 48 + ms * 16 + (lane >> 2);
                float a0f = sF[(k0 + (lane & 3)) * 100 + mcol];
                float a1f = sF[(k0 + (lane & 3)) * 100 + mcol + 8];
                float a2f = sF[(k0 + 4 + (lane & 3)) * 100 + mcol];
                float a3f = sF[(k0 + 4 + (lane & 3)) * 100 + mcol + 8];
                if (dw == 0) { sk[ms][0] += a0f + a2f; sk[ms][1] += a1f + a3f; }
#pragma unroll
                for (int ns = 0; ns < 2; ns++)
                    mma8(acc[ms][ns], __float_as_uint(a0f), __float_as_uint(a1f),
                         __float_as_uint(a2f), __float_as_uint(a3f), bf0[ns], bf1[ns]);
            }
        }
        __syncthreads();
    }

#pragma unroll
    for (int ms = 0; ms < 3; ms++)
#pragma unroll
        for (int hh = 0; hh < 2; hh++) {
            float v = sk[ms][hh];
            v += __shfl_xor_sync(0xffffffffu, v, 1);
            v += __shfl_xor_sync(0xffffffffu, v, 2);
            if (dw == 0 && (lane & 3) == 0) {
                int m = m0 + mw * 48 + ms * 16 + (lane >> 2) + hh * 8;
                g_ksp[((size_t)head * NC + chunk) * MPAD + m] = v;
            }
        }
    float* outp = g_kvp + ((size_t)head * NC + chunk) * MPAD * 64;
#pragma unroll
    for (int ms = 0; ms < 3; ms++) {
        int mr = m0 + mw * 48 + ms * 16 + (lane >> 2);
#pragma unroll
        for (int ns = 0; ns < 2; ns++) {
            int col = dw * 16 + ns * 8 + (lane & 3) * 2;
            *(float2*)&outp[(size_t)mr * 64 + col] = make_float2(acc[ms][ns][0], acc[ms][ns][1]);
            *(float2*)&outp[(size_t)(mr + 8) * 64 + col] = make_float2(acc[ms][ns][2], acc[ms][ns][3]);
        }
    }
}

__global__ void kv_reduce2()
{
    int idx = blockIdx.x * blockDim.x + threadIdx.x;
    const int TOT = NHEAD * MPAD * 64;
    if (idx < TOT) {
        int head = idx / (MPAD * 64), rem = idx % (MPAD * 64);
        int m = rem >> 6, d = rem & 63;
        float s = 0.f;
        for (int c = 0; c < NC; c++)
            s += g_kvp[((size_t)(head * NC + c) * MPAD + m) * 64 + d];
        g_kvT[(head * 64 + d) * MPAD + m] = rtf(s);
    } else if (idx < TOT + NHEAD * MPAD) {
        int r = idx - TOT, head = r / MPAD, m = r % MPAD;
        float s = 0.f;
        for (int c = 0; c < NC; c++)
            s += g_ksp[(size_t)(head * NC + c) * MPAD + m];
        g_ksum[head * MPAD + m] = s;
    }
}

// ======================= fused qf-feature + FAVOR+ out-GEMM =======================
__global__ __launch_bounds__(256) void tc_attn(const float* __restrict__ proj)
{
    extern __shared__ float sm[];
    float* sQ = sm;                       // 128*68
    float* sF = sQ + 128 * 68;            // 2 * 128*36
    float* sP = sF + 2 * 128 * 36;        // 2 * 32*68
    float* sKV = sP + 2 * 32 * 68;        // 2 * 64*36
    float* sKS = sKV + 2 * 64 * 36;       // 288
    float* sDinv = sKS + MPAD;            // 128

    const int t = threadIdx.x, lane = t & 31, warp = t >> 5;
    const int wr = warp >> 1, wc = warp & 1;
    const int n0 = blockIdx.x * 128, head = blockIdx.y;

    {
        unsigned ua = (unsigned)__cvta_generic_to_shared(sQ);
#pragma unroll
        for (int i = 0; i < 8; i++) {
            int id = t + 256 * i, r = id >> 4, c4 = (id & 15) * 4;
            cpa16(ua + (r * 68 + c4) * 4, g_qkv + (size_t)(n0 + r) * QKF + head * 64 + c4,
                  (n0 + r) < NNODES);
        }
        unsigned up = (unsigned)__cvta_generic_to_shared(sP);
        unsigned uk = (unsigned)__cvta_generic_to_shared(sKV);
#pragma unroll
        for (int i = 0; i < 2; i++) {
            int id = t + 256 * i, r = id >> 4, c4 = (id & 15) * 4;
            cpa16(up + (r * 68 + c4) * 4, proj + (size_t)r * HDIM + c4, true);
        }
#pragma unroll
        for (int i = 0; i < 2; i++) {
            int id = t + 256 * i, r = id >> 3, c4 = (id & 7) * 4;
            cpa16(uk + (r * 36 + c4) * 4, g_kvT + (size_t)(head * 64 + r) * MPAD + c4, true);
        }
        cp_commit();
    }
    for (int i = t; i < MPAD; i += 256) sKS[i] = g_ksum[head * MPAD + i];

    float acc[2][4][4];
#pragma unroll
    for (int ms = 0; ms < 2; ms++)
#pragma unroll
        for (int ns = 0; ns < 4; ns++)
#pragma unroll
            for (int j = 0; j < 4; j++) acc[ms][ns][j] = 0.f;
    float facc[2][2][4];
#pragma unroll
    for (int ms = 0; ms < 2; ms++)
#pragma unroll
        for (int ns = 0; ns < 2; ns++)
#pragma unroll
            for (int j = 0; j < 4; j++) facc[ms][ns][j] = 0.f;
    float dot = 0.f;

    for (int s = 0; s < 9; s++) {
        if (s < 8) {
            int b = (s + 1) & 1;
            unsigned up = (unsigned)__cvta_generic_to_shared(sP + b * 32 * 68);
            unsigned uk = (unsigned)__cvta_generic_to_shared(sKV + b * 64 * 36);
#pragma unroll
            for (int i = 0; i < 2; i++) {
                int id = t + 256 * i, r = id >> 4, c4 = (id & 15) * 4;
                cpa16(up + (r * 68 + c4) * 4, proj + (size_t)((s + 1) * 32 + r) * HDIM + c4, true);
            }
#pragma unroll
            for (int i = 0; i < 2; i++) {
                int id = t + 256 * i, r = id >> 3, c4 = (id & 7) * 4;
                cpa16(uk + (r * 36 + c4) * 4,
                      g_kvT + (size_t)(head * 64 + r) * MPAD + (s + 1) * 32 + c4, true);
            }
            cp_commit(); cp_wait<1>();
        } else {
            cp_wait<0>();
        }
        __syncthreads();
        float* cP = sP + (s & 1) * 32 * 68;
        float* cKV = sKV + (s & 1) * 64 * 36;
        float* cF = sF + (s & 1) * 128 * 36;

#pragma unroll
        for (int kk = 0; kk < 8; kk++) {
            int k0 = kk * 8;
            unsigned bf0[2], bf1[2];
#pragma unroll
            for (int ns = 0; ns < 2; ns++) {
                int col = wc * 16 + ns * 8 + (lane >> 2);
                bf0[ns] = __float_as_uint(cP[col * 68 + k0 + (lane & 3)]);
                bf1[ns] = __float_as_uint(cP[col * 68 + k0 + 4 + (lane & 3)]);
            }
#pragma unroll
            for (int ms = 0; ms < 2; ms++) {
                int row = wr * 32 + ms * 16 + (lane >> 2);
                unsigned a0 = __float_as_uint(sQ[row * 68 + k0 + (lane & 3)]);
                unsigned a1 = __float_as_uint(sQ[(row + 8) * 68 + k0 + (lane & 3)]);
                unsigned a2 = __float_as_uint(sQ[row * 68 + k0 + 4 + (lane & 3)]);
                unsigned a3 = __float_as_uint(sQ[(row + 8) * 68 + k0 + 4 + (lane & 3)]);
#pragma unroll
                for (int ns = 0; ns < 2; ns++)
                    mma8(facc[ms][ns], a0, a1, a2, a3, bf0[ns], bf1[ns]);
            }
        }
#pragma unroll
        for (int ms = 0; ms < 2; ms++) {
            int row = wr * 32 + ms * 16 + (lane >> 2);
#pragma unroll
            for (int ns = 0; ns < 2; ns++) {
                int colL = wc * 16 + ns * 8 + (lane & 3) * 2;
                int gm = s * 32 + colL;
                float v0 = (gm < MRF)     ? rtf(fmaxf(facc[ms][ns][0], 0.f) + EPSK) : 0.f;
                float v1 = (gm + 1 < MRF) ? rtf(fmaxf(facc[ms][ns][1], 0.f) + EPSK) : 0.f;
                float v2 = (gm < MRF)     ? rtf(fmaxf(facc[ms][ns][2], 0.f) + EPSK) : 0.f;
                float v3 = (gm + 1 < MRF) ? rtf(fmaxf(facc[ms][ns][3], 0.f) + EPSK) : 0.f;
                *(float2*)&cF[row * 36 + colL] = make_float2(v0, v1);
                *(float2*)&cF[(row + 8) * 36 + colL] = make_float2(v2, v3);
                facc[ms][ns][0] = facc[ms][ns][1] = facc[ms][ns][2] = facc[ms][ns][3] = 0.f;
            }
        }
        __syncthreads();
        {
            int rr = t >> 1, kh = (t & 1) * 16;
#pragma unroll
            for (int j = 0; j < 4; j++) {
                float4 fv = *(const float4*)&cF[rr * 36 + kh + j * 4];
                float4 kv = *(const float4*)&sKS[s * 32 + kh + j * 4];
                dot += fv.x * kv.x + fv.y * kv.y + fv.z * kv.z + fv.w * kv.w;
            }
        }
#pragma unroll
        for (int kk = 0; kk < 4; kk++) {
            int k0 = kk * 8;
            unsigned bf0[4], bf1[4];
#pragma unroll
            for (int ns = 0; ns < 4; ns++) {
                int col = wc * 32 + ns * 8 + (lane >> 2);
                bf0[ns] = __float_as_uint(cKV[col * 36 + k0 + (lane & 3)]);
                bf1[ns] = __float_as_uint(cKV[col * 36 + k0 + 4 + (lane & 3)]);
            }
#pragma unroll
            for (int ms = 0; ms < 2; ms++) {
                int row = wr * 32 + ms * 16 + (lane >> 2);
                unsigned a0 = __float_as_uint(cF[row * 36 + k0 + (lane & 3)]);
                unsigned a1 = __float_as_uint(cF[(row + 8) * 36 + k0 + (lane & 3)]);
                unsigned a2 = __float_as_uint(cF[row * 36 + k0 + 4 + (lane & 3)]);
                unsigned a3 = __float_as_uint(cF[(row + 8) * 36 + k0 + 4 + (lane & 3)]);
#pragma unroll
                for (int ns = 0; ns < 4; ns++)
                    mma8(acc[ms][ns], a0, a1, a2, a3, bf0[ns], bf1[ns]);
            }
        }
        __syncthreads();
    }

    dot += __shfl_xor_sync(0xffffffffu, dot, 1);
    if ((t & 1) == 0) sDinv[t >> 1] = 1.0f / dot;
    __syncthreads();

#pragma unroll
    for (int ms = 0; ms < 2; ms++) {
        int lr = wr * 32 + ms * 16 + (lane >> 2);
#pragma unroll
        for (int half = 0; half < 2; half++) {
            int row = n0 + lr + half * 8;
            if (row >= NNODES) continue;
            float sc = sDinv[lr + half * 8];
#pragma unroll
            for (int ns = 0; ns < 4; ns++) {
                int col = wc * 32 + ns * 8 + (lane & 3) * 2;
                float v0 = rtf(acc[ms][ns][half * 2 + 0] * sc);
                float v1 = rtf(acc[ms][ns][half * 2 + 1] * sc);
                *(float2*)&g_attn[(size_t)row * FDIM + head * 64 + col] = make_float2(v0, v1);
            }
        }
    }
}

// ======================= fused Wo-GEMM + bias + LayerNorm =======================
// block = 64 nodes x full 192 output cols, 8 warps (2x4), warp tile 32x48.
__device__ __forceinline__ void stage_woln(float* sA, const float* A, const float* B,
                                           int n0, int t, int kb)
{
    float* sB = sA + 64 * 36;
    unsigned ua = (unsigned)__cvta_generic_to_shared(sA);
    unsigned ub = (unsigned)__cvta_generic_to_shared(sB);
#pragma unroll
    for (int i = 0; i < 2; i++) {
        int id = t + 256 * i, r = id >> 3, c4 = (id & 7) * 4;
        cpa16(ua + (r * 36 + c4) * 4, A + (size_t)(n0 + r) * FDIM + kb + c4, (n0 + r) < NNODES);
    }
#pragma unroll
    for (int i = 0; i < 6; i++) {
        int id = t + 256 * i, r = id >> 3, c4 = (id & 7) * 4;
        cpa16(ub + (r * 36 + c4) * 4, B + (size_t)r * FDIM + kb + c4, true);
    }
}

__global__ __launch_bounds__(256) void tc_woln(
    const float* __restrict__ A, const float* __restrict__ B,
    const float* __restrict__ bo, const float* __restrict__ gamma,
    const float* __restrict__ beta, float* __restrict__ C, int relu_round)
{
    extern __shared__ float sm[];
    constexpr int STW = (64 + 192) * 36;   // 9216
    float* sPar = sm + 2 * STW;            // bo 192 | gamma 192 | beta 192
    const int t = threadIdx.x, lane = t & 31, warp = t >> 5;
    const int wr = warp >> 2, wc = warp & 3;
    const int n0 = blockIdx.x * 64;

    for (int i = t; i < FDIM; i += 256) {
        sPar[i] = bo[i]; sPar[FDIM + i] = gamma[i]; sPar[2 * FDIM + i] = beta[i];
    }

    float acc[2][6][4];
#pragma unroll
    for (int ms = 0; ms < 2; ms++)
#pragma unroll
        for (int ns = 0; ns < 6; ns++)
#pragma unroll
            for (int j = 0; j < 4; j++) acc[ms][ns][j] = 0.f;

    stage_woln(sm, A, B, n0, t, 0);
    cp_commit();
    for (int it = 0; it < 6; it++) {
        if (it < 5) {
            stage_woln(sm + ((it + 1) & 1) * STW, A, B, n0, t, (it + 1) << 5);
            cp_commit(); cp_wait<1>();
        } else {
            cp_wait<0>();
        }
        __syncthreads();
        float* sA = sm + (it & 1) * STW; float* sB = sA + 64 * 36;
#pragma unroll
        for (int kk = 0; kk < 4; kk++) {
            int k0 = kk * 8;
            unsigned bf0[6], bf1[6];
#pragma unroll
            for (int ns = 0; ns < 6; ns++) {
                int col = wc * 48 + ns * 8 + (lane >> 2);
                bf0[ns] = __float_as_uint(sB[col * 36 + k0 + (lane & 3)]);
                bf1[ns] = __float_as_uint(sB[col * 36 + k0 + 4 + (lane & 3)]);
            }
#pragma unroll
            for (int ms = 0; ms < 2; ms++) {
                int row = wr * 32 + ms * 16 + (lane >> 2);
                unsigned a0 = __float_as_uint(sA[row * 36 + k0 + (lane & 3)]);
                unsigned a1 = __float_as_uint(sA[(row + 8) * 36 + k0 + (lane & 3)]);
                unsigned a2 = __float_as_uint(sA[row * 36 + k0 + 4 + (lane & 3)]);
                unsigned a3 = __float_as_uint(sA[(row + 8) * 36 + k0 + 4 + (lane & 3)]);
#pragma unroll
                for (int ns = 0; ns < 6; ns++)
                    mma8(acc[ms][ns], a0, a1, a2, a3, bf0[ns], bf1[ns]);
            }
        }
        __syncthreads();
    }

    // store C tile (+bias) into retired staging smem, stride 196
    float* sC = sm;
#pragma unroll
    for (int ms = 0; ms < 2; ms++) {
#pragma unroll
        for (int half = 0; half < 2; half++) {
            int row = wr * 32 + ms * 16 + (lane >> 2) + half * 8;
#pragma unroll
            for (int ns = 0; ns < 6; ns++) {
                int col = wc * 48 + ns * 8 + (lane & 3) * 2;
                float v0 = acc[ms][ns][half * 2 + 0] + sPar[col];
                float v1 = acc[ms][ns][half * 2 + 1] + sPar[col + 1];
                *(float2*)&sC[row * 196 + col] = make_float2(v0, v1);
            }
        }
    }
    __syncthreads();

    // LayerNorm: each warp handles 8 rows
#pragma unroll
    for (int rr = 0; rr < 8; rr++) {
        int row = rr * 8 + warp;
        int gn = n0 + row;
        float x[6], s = 0.f;
#pragma unroll
        for (int i = 0; i < 6; i++) { x[i] = sC[row * 196 + lane + 32 * i]; s += x[i]; }
#pragma unroll
        for (int o = 16; o; o >>= 1) s += __shfl_xor_sync(0xffffffffu, s, o);
        float mu = s * (1.0f / FDIM), var = 0.f;
#pragma unroll
        for (int i = 0; i < 6; i++) { float d = x[i] - mu; var += d * d; }
#pragma unroll
        for (int o = 16; o; o >>= 1) var += __shfl_xor_sync(0xffffffffu, var, o);
        float inv = rsqrtf(var * (1.0f / FDIM) + LNEPS);
        if (gn < NNODES) {
            float* orow = C + (size_t)gn * FDIM;
#pragma unroll
            for (int i = 0; i < 6; i++) {
                int o = lane + 32 * i;
                float y = (x[i] - mu) * inv * sPar[FDIM + o] + sPar[2 * FDIM + o];
                if (relu_round) y = rtf(fmaxf(y, 0.f));
                orow[o] = y;
            }
        }
    }
}

// ======================= misc =======================
__global__ void pack_weights(const float* __restrict__ Wq, const float* __restrict__ Wk,
                             const float* __restrict__ Wv, const float* __restrict__ Wo,
                             const float* __restrict__ proj)
{
    int idx = blockIdx.x * blockDim.x + threadIdx.x;
    const int S1 = NLAYER * QKF * FDIM, S2 = NLAYER * FDIM * FDIM, S3 = NLAYER * MPAD * HDIM;
    if (idx < S1) {
        int l = idx / (QKF * FDIM), r = idx % (QKF * FDIM);
        int row = r / FDIM, col = r % FDIM;
        const float* W = (row < 192) ? Wq : (row < 384) ? Wk : Wv;
        g_wqkv[idx] = rtf(W[((size_t)l * FDIM + row % 192) * FDIM + col]);
    } else if (idx < S1 + S2) {
        g_wor[idx - S1] = rtf(Wo[idx - S1]);
    } else if (idx < S1 + S2 + S3) {
        int j = idx - S1 - S2;
        int l = j / (MPAD * HDIM), r = j % (MPAD * HDIM);
        int row = r / HDIM, col = r % HDIM;
        g_projr[j] = (row < MRF) ? rtf(proj[((size_t)l * MRF + row) * HDIM + col]) : 0.f;
    }
}

__global__ void round_arr(const float* __restrict__ src, float* __restrict__ dst, int n4)
{
    int i = blockIdx.x * blockDim.x + threadIdx.x;
    if (i < n4) {
        float4 v = ((const float4*)src)[i];
        v.x = rtf(v.x); v.y = rtf(v.y); v.z = rtf(v.z); v.w = rtf(v.w);
        ((float4*)dst)[i] = v;
    }
}

extern "C" void kernel_launch(void* const* d_in, const int* in_sizes, int n_in,
                              void* d_out, int out_size)
{
    const float* h0    = (const float*)d_in[0];
    const float* eattr = (const float*)d_in[1];
    const float* Wq = (const float*)d_in[3];
    const float* Wk = (const float*)d_in[4];
    const float* Wv = (const float*)d_in[5];
    const float* Wo = (const float*)d_in[6];
    const float* bo = (const float*)d_in[7];
    const float* ga = (const float*)d_in[8];
    const float* be = (const float*)d_in[9];
    const float* pr = (const float*)d_in[10];
    float* out = (float*)d_out;

    float *qkv, *attn, *hbuf, *wqkv, *wor, *projr;
    cudaGetSymbolAddress((void**)&qkv, g_qkv);
    cudaGetSymbolAddress((void**)&attn, g_attn);
    cudaGetSymbolAddress((void**)&hbuf, g_h);
    cudaGetSymbolAddress((void**)&wqkv, g_wqkv);
    cudaGetSymbolAddress((void**)&wor, g_wor);
    cudaGetSymbolAddress((void**)&projr, g_projr);

    const int smem96 = ((128 + 96) * 36 * 2) * 4;                                   // 64512
    const int smemkvf = (96 * 68 + 2 * 32 * 68 + 2 * 32 * 68 + 32 * 100) * 4;       // 73728
    const int smemattn = (128 * 68 + 2 * 128 * 36 + 2 * 32 * 68 + 2 * 64 * 36 + MPAD + 128) * 4;
    const int smemwoln = (2 * (64 + 192) * 36 + 3 * FDIM) * 4;                      // 76032
    cudaFuncSetAttribute(tc_gemm2<96>, cudaFuncAttributeMaxDynamicSharedMemorySize, smem96);
    cudaFuncSetAttribute(tc_kvf, cudaFuncAttributeMaxDynamicSharedMemorySize, smemkvf);
    cudaFuncSetAttribute(tc_attn, cudaFuncAttributeMaxDynamicSharedMemorySize, smemattn);
    cudaFuncSetAttribute(tc_woln, cudaFuncAttributeMaxDynamicSharedMemorySize, smemwoln);

    cudaMemcpyAsync(out + (size_t)NNODES * FDIM, eattr,
                    (size_t)EEDGE * 8 * sizeof(float), cudaMemcpyDeviceToDevice);

    const int PACKN = NLAYER * (QKF * FDIM + FDIM * FDIM + MPAD * HDIM);
    pack_weights<<<(PACKN + 255) / 256, 256>>>(Wq, Wk, Wv, Wo, pr);
    round_arr<<<(NNODES * FDIM / 4 + 255) / 256, 256>>>(h0, hbuf, NNODES * FDIM / 4);

    const int REDN = NHEAD * MPAD * 64 + NHEAD * MPAD;
    for (int l = 0; l < NLAYER; l++) {
        float* hout = (l == NLAYER - 1) ? out : hbuf;
        tc_gemm2<96><<<dim3(6, NB128), 256, smem96>>>(
            hbuf, FDIM, wqkv + (size_t)l * QKF * FDIM, FDIM, QKF, qkv, QKF, FDIM);
        tc_kvf<<<dim3(3, NC, 3), 256, smemkvf>>>(projr + (size_t)l * MPAD * HDIM);
        kv_reduce2<<<(REDN + 255) / 256, 256>>>();
        tc_attn<<<dim3(NB128, 3), 256, smemattn>>>(projr + (size_t)l * MPAD * HDIM);
        tc_woln<<<NB64, 256, smemwoln>>>(
            attn, wor + (size_t)l * FDIM * FDIM, bo + l * FDIM,
            ga + l * FDIM, be + l * FDIM, hout, (l < NLAYER - 1) ? 1 : 0);
    }
}